// round 11
// baseline (speedup 1.0000x reference)
#include <cuda_runtime.h>
#include <cstdint>

#define BB 4
#define CC 64
#define HH 256
#define WWID 512
#define MAXD 48
#define DD 97          // 2*MAXD+1
#define WT 128         // W tile per CTA
#define RW 224         // WT + 2*MAXD
#define NTHREADS 256
#define SMEM_BYTES (CC*RW*4)   // 57344 B (56 KB) — R tile only
#define HSTRIDE ((size_t)HH*WWID)

using u64 = unsigned long long;

__device__ __forceinline__ u64 pack2(unsigned lo, unsigned hi) {
    u64 d; asm("mov.b64 %0, {%1, %2};" : "=l"(d) : "r"(lo), "r"(hi)); return d;
}
__device__ __forceinline__ void unpack2(u64 v, unsigned &lo, unsigned &hi) {
    asm("mov.b64 {%0, %1}, %2;" : "=r"(lo), "=r"(hi) : "l"(v));
}
__device__ __forceinline__ void ffma2(u64 &acc, u64 a, u64 b) {
    asm("fma.rn.f32x2 %0, %1, %2, %0;" : "+l"(acc) : "l"(a), "l"(b));
}
__device__ __forceinline__ u64 mul2(u64 a, u64 b) {
    u64 d; asm("mul.rn.f32x2 %0, %1, %2;" : "=l"(d) : "l"(a), "l"(b)); return d;
}
__device__ __forceinline__ unsigned lou(u64 v){ unsigned a,b; unpack2(v,a,b); return a; }
__device__ __forceinline__ unsigned hiu(u64 v){ unsigned a,b; unpack2(v,a,b); return b; }

extern __shared__ float smem[];

// L: 8 floats via 2x LDG.128 (16 lanes share each address -> broadcast)
__device__ __forceinline__ void load_L(const float* __restrict__ LgT, int c, u64* L)
{
    ulonglong2 a = *(const ulonglong2*)(LgT + (size_t)c * HSTRIDE);
    ulonglong2 b = *(const ulonglong2*)(LgT + (size_t)c * HSTRIDE + 4);
    L[0] = a.x; L[1] = a.y; L[2] = b.x; L[3] = b.y;
}

// R: 14 floats as 7 aligned u64 pairs (LDS.64, half-warp conflict-free:
// (4tw - 3td + const + m) mod 16 distinct over td=0..15 since gcd(3,16)=1)
__device__ __forceinline__ void load_R(const float* RrowP, int c, u64* RP)
{
    #pragma unroll
    for (int m = 0; m < 7; m++)
        RP[m] = *(const u64*)(RrowP + c * RW + 2 * m);
}

// One channel: j = 6*td + jj, w = 8*tw + ww, r[t] at RP-float-offset t+1,
// t = ww + 5 - jj.
// even jj=2je: out pair (ww,ww+1), ww=2wp -> t odd -> native pair RP[wp+3-je]
// odd  jj=2jo+1: acc re-paired (2p+1,2p+2) -> native pair RP[p+3-jo];
//   ends: w=0 -> hi(RP[2-jo]), w=7 -> lo(RP[6-jo])
__device__ __forceinline__ void compute_c(u64 Ae[3][4], u64 Ao[3][3], u64 Sp[3],
                                          const u64* L, const u64* RP)
{
    u64 Lodd[3];
    Lodd[0] = pack2(hiu(L[0]), lou(L[1]));  // (l1,l2)
    Lodd[1] = pack2(hiu(L[1]), lou(L[2]));  // (l3,l4)
    Lodd[2] = pack2(hiu(L[2]), lou(L[3]));  // (l5,l6)
    u64 l07 = pack2(lou(L[0]), hiu(L[3]));  // (l0,l7)
    #pragma unroll
    for (int je = 0; je < 3; je++)
        #pragma unroll
        for (int wp = 0; wp < 4; wp++)
            ffma2(Ae[je][wp], L[wp], RP[wp + 3 - je]);
    #pragma unroll
    for (int jo = 0; jo < 3; jo++) {
        #pragma unroll
        for (int p = 0; p < 3; p++)
            ffma2(Ao[jo][p], Lodd[p], RP[p + 3 - jo]);
        u64 rr = pack2(hiu(RP[2 - jo]), lou(RP[6 - jo]));
        ffma2(Sp[jo], l07, rr);
    }
}

__global__ void __launch_bounds__(NTHREADS, 2)
cost_volume_kernel(const float* __restrict__ Lg0,
                   const float* __restrict__ Rg0,
                   float* __restrict__ out)
{
    float* Rs = smem;   // [CC][RW], Rs[c][i] = r[w0-48+i]

    const int w0  = blockIdx.x * WT;
    const int h   = blockIdx.y;
    const int b   = blockIdx.z;
    const int tid = threadIdx.x;

    // ---------------- stage R tile with zero-padded halo ----------------
    const float* Rg = Rg0 + ((size_t)(b * CC) * HH + h) * WWID;
    {
        const int NV = CC * RW / 4;   // 3584 float4
        #pragma unroll 2
        for (int idx = tid; idx < NV; idx += NTHREADS) {
            int c = idx / 56;
            int k = (idx - c * 56) << 2;
            int gw = w0 - MAXD + k;
            const float* rr = Rg + (size_t)c * HSTRIDE;
            float4 v;
            if (gw >= 0 && gw + 3 < WWID) {
                v = *(const float4*)(rr + gw);
            } else {
                v.x = (gw     >= 0 && gw     < WWID) ? rr[gw]     : 0.f;
                v.y = (gw + 1 >= 0 && gw + 1 < WWID) ? rr[gw + 1] : 0.f;
                v.z = (gw + 2 >= 0 && gw + 2 < WWID) ? rr[gw + 2] : 0.f;
                v.w = (gw + 3 >= 0 && gw + 3 < WWID) ? rr[gw + 3] : 0.f;
            }
            *(float4*)(Rs + c * RW + k) = v;
        }
    }
    __syncthreads();

    // ---------------- compute: 8(w) x 6(j) register tile per thread -------
    // td = tid&15 (j group; 16 adjacent lanes share tw -> L LDG broadcast),
    // tw = tid>>4. j = 6*td + jj (jj 0..5) covers j 0..95; j=96 separate.
    // Rs index i = w_local + 96 - j; per-thread pair-aligned base:
    // baseP = 8*tw - 6*td + 90 (even, >= 0; max float = 223 < RW).
    const int td = tid & 15;
    const int tw = tid >> 4;
    const float* RrowP = Rs + (8 * tw - 6 * td + 90);

    u64 Ae[3][4], Ao[3][3], Sp[3];
    #pragma unroll
    for (int j3 = 0; j3 < 3; j3++) {
        #pragma unroll
        for (int wp = 0; wp < 4; wp++) Ae[j3][wp] = 0ULL;
        #pragma unroll
        for (int p = 0; p < 3; p++)   Ao[j3][p] = 0ULL;
        Sp[j3] = 0ULL;
    }

    const float* __restrict__ LgT =
        Lg0 + ((size_t)(b * CC) * HH + h) * WWID + w0 + 8 * tw;

    // L prefetched one channel ahead (register double buffer); R unbuffered
    // (LDS latency covered by 16 warps/SM).
    u64 LA[4], LB[4];
    load_L(LgT, 0, LA);
    #pragma unroll 1
    for (int c = 0; c < CC; c += 2) {
        load_L(LgT, c + 1, LB);
        {
            u64 RP[7]; load_R(RrowP, c, RP);
            compute_c(Ae, Ao, Sp, LA, RP);
        }
        load_L(LgT, (c + 2 < CC) ? c + 2 : 0, LA);
        {
            u64 RP[7]; load_R(RrowP, c + 1, RP);
            compute_c(Ae, Ao, Sp, LB, RP);
        }
    }

    // ---------------- epilogue: scale by 1/64 and store -------------------
    const u64 scale2 = pack2(0x3C800000u, 0x3C800000u);  // (1/64, 1/64)
    float* outBase = out + (((size_t)b * DD) * HH + h) * WWID + w0 + 8 * tw;
    #pragma unroll
    for (int j3 = 0; j3 < 3; j3++) {
        {   // even jj = 2*j3
            int j = 6 * td + 2 * j3;
            float* o = outBase + (size_t)j * HSTRIDE;
            u64 v0 = mul2(Ae[j3][0], scale2), v1 = mul2(Ae[j3][1], scale2);
            *(uint4*)(o)     = make_uint4(lou(v0), hiu(v0), lou(v1), hiu(v1));
            u64 v2 = mul2(Ae[j3][2], scale2), v3 = mul2(Ae[j3][3], scale2);
            *(uint4*)(o + 4) = make_uint4(lou(v2), hiu(v2), lou(v3), hiu(v3));
        }
        {   // odd jj = 2*j3+1: {s0, o0.lo, o0.hi, o1.lo | o1.hi, o2.lo, o2.hi, s7}
            int j = 6 * td + 2 * j3 + 1;
            float* o = outBase + (size_t)j * HSTRIDE;
            u64 p0 = mul2(Ao[j3][0], scale2);
            u64 p1 = mul2(Ao[j3][1], scale2);
            u64 p2 = mul2(Ao[j3][2], scale2);
            u64 ss = mul2(Sp[j3], scale2);
            *(uint4*)(o)     = make_uint4(lou(ss), lou(p0), hiu(p0), lou(p1));
            *(uint4*)(o + 4) = make_uint4(hiu(p1), lou(p2), hiu(p2), hiu(ss));
        }
    }

    // ---------------- j = 96 plane (d = +48): i = w_local ------------------
    if (tid < WT) {
        const float* Lg96 = Lg0 + ((size_t)(b * CC) * HH + h) * WWID + w0 + tid;
        float s = 0.f;
        #pragma unroll 8
        for (int c = 0; c < CC; c++)
            s += Lg96[(size_t)c * HSTRIDE] * Rs[c * RW + tid];
        out[(((size_t)b * DD + 96) * HH + h) * WWID + w0 + tid] = s * 0.015625f;
    }
}

extern "C" void kernel_launch(void* const* d_in, const int* in_sizes, int n_in,
                              void* d_out, int out_size)
{
    const float* L = (const float*)d_in[0];
    const float* R = (const float*)d_in[1];
    float* out = (float*)d_out;
    cudaFuncSetAttribute(cost_volume_kernel,
                         cudaFuncAttributeMaxDynamicSharedMemorySize, SMEM_BYTES);
    dim3 grid(WWID / WT, HH, BB);   // (4, 256, 4) = 4096 CTAs
    cost_volume_kernel<<<grid, NTHREADS, SMEM_BYTES>>>(L, R, out);
}

// round 12
// speedup vs baseline: 1.0008x; 1.0008x over previous
#include <cuda_runtime.h>
#include <cstdint>

#define BB 4
#define CC 64
#define HH 256
#define WWID 512
#define MAXD 48
#define DD 97          // 2*MAXD+1
#define WT 128         // W tile per CTA
#define RW 224         // WT + 2*MAXD
#define NTHREADS 256
#define SMEM_BYTES (CC*RW*4)   // 57344 B (56 KB) — R tile only
#define HSTRIDE ((size_t)HH*WWID)

using u64 = unsigned long long;

__device__ __forceinline__ u64 pack2(unsigned lo, unsigned hi) {
    u64 d; asm("mov.b64 %0, {%1, %2};" : "=l"(d) : "r"(lo), "r"(hi)); return d;
}
__device__ __forceinline__ void unpack2(u64 v, unsigned &lo, unsigned &hi) {
    asm("mov.b64 {%0, %1}, %2;" : "=r"(lo), "=r"(hi) : "l"(v));
}
__device__ __forceinline__ void ffma2(u64 &acc, u64 a, u64 b) {
    asm("fma.rn.f32x2 %0, %1, %2, %0;" : "+l"(acc) : "l"(a), "l"(b));
}
__device__ __forceinline__ u64 mul2(u64 a, u64 b) {
    u64 d; asm("mul.rn.f32x2 %0, %1, %2;" : "=l"(d) : "l"(a), "l"(b)); return d;
}
__device__ __forceinline__ unsigned lou(u64 v){ unsigned a,b; unpack2(v,a,b); return a; }
__device__ __forceinline__ unsigned hiu(u64 v){ unsigned a,b; unpack2(v,a,b); return b; }

extern __shared__ float smem[];

// L: 8 floats via 2x LDG.128 (16 lanes share each address -> broadcast)
__device__ __forceinline__ void load_L(const float* __restrict__ LgT, int c, u64* L)
{
    ulonglong2 a = *(const ulonglong2*)(LgT + (size_t)c * HSTRIDE);
    ulonglong2 b = *(const ulonglong2*)(LgT + (size_t)c * HSTRIDE + 4);
    L[0] = a.x; L[1] = a.y; L[2] = b.x; L[3] = b.y;
}

// R: 14 floats as 7 aligned u64 pairs (LDS.64, half-warp conflict-free:
// (4tw - 3td + const + m) mod 16 distinct over td=0..15 since gcd(3,16)=1)
__device__ __forceinline__ void load_R(const float* RrowP, int c, u64* RP)
{
    #pragma unroll
    for (int m = 0; m < 7; m++)
        RP[m] = *(const u64*)(RrowP + c * RW + 2 * m);
}

// One channel: j = 6*td + jj, w = 8*tw + ww, r[t] at RP-float-offset t+1,
// t = ww + 5 - jj.
// even jj=2je: out pair (ww,ww+1), ww=2wp -> t odd -> native pair RP[wp+3-je]
// odd  jj=2jo+1: acc re-paired (2p+1,2p+2) -> native pair RP[p+3-jo];
//   ends: w=0 -> hi(RP[2-jo]), w=7 -> lo(RP[6-jo])
__device__ __forceinline__ void compute_c(u64 Ae[3][4], u64 Ao[3][3], u64 Sp[3],
                                          const u64* L, const u64* RP)
{
    u64 Lodd[3];
    Lodd[0] = pack2(hiu(L[0]), lou(L[1]));  // (l1,l2)
    Lodd[1] = pack2(hiu(L[1]), lou(L[2]));  // (l3,l4)
    Lodd[2] = pack2(hiu(L[2]), lou(L[3]));  // (l5,l6)
    u64 l07 = pack2(lou(L[0]), hiu(L[3]));  // (l0,l7)
    #pragma unroll
    for (int je = 0; je < 3; je++)
        #pragma unroll
        for (int wp = 0; wp < 4; wp++)
            ffma2(Ae[je][wp], L[wp], RP[wp + 3 - je]);
    #pragma unroll
    for (int jo = 0; jo < 3; jo++) {
        #pragma unroll
        for (int p = 0; p < 3; p++)
            ffma2(Ao[jo][p], Lodd[p], RP[p + 3 - jo]);
        u64 rr = pack2(hiu(RP[2 - jo]), lou(RP[6 - jo]));
        ffma2(Sp[jo], l07, rr);
    }
}

__global__ void __launch_bounds__(NTHREADS, 2)
cost_volume_kernel(const float* __restrict__ Lg0,
                   const float* __restrict__ Rg0,
                   float* __restrict__ out)
{
    float* Rs = smem;   // [CC][RW], Rs[c][i] = r[w0-48+i]

    const int w0  = blockIdx.x * WT;
    const int h   = blockIdx.y;
    const int b   = blockIdx.z;
    const int tid = threadIdx.x;

    // ---------------- stage R tile with zero-padded halo ----------------
    const float* Rg = Rg0 + ((size_t)(b * CC) * HH + h) * WWID;
    {
        const int NV = CC * RW / 4;   // 3584 float4
        #pragma unroll 2
        for (int idx = tid; idx < NV; idx += NTHREADS) {
            int c = idx / 56;
            int k = (idx - c * 56) << 2;
            int gw = w0 - MAXD + k;
            const float* rr = Rg + (size_t)c * HSTRIDE;
            float4 v;
            if (gw >= 0 && gw + 3 < WWID) {
                v = *(const float4*)(rr + gw);
            } else {
                v.x = (gw     >= 0 && gw     < WWID) ? rr[gw]     : 0.f;
                v.y = (gw + 1 >= 0 && gw + 1 < WWID) ? rr[gw + 1] : 0.f;
                v.z = (gw + 2 >= 0 && gw + 2 < WWID) ? rr[gw + 2] : 0.f;
                v.w = (gw + 3 >= 0 && gw + 3 < WWID) ? rr[gw + 3] : 0.f;
            }
            *(float4*)(Rs + c * RW + k) = v;
        }
    }
    __syncthreads();

    // ---------------- compute: 8(w) x 6(j) register tile per thread -------
    // td = tid&15 (j group; 16 adjacent lanes share tw -> L LDG broadcast),
    // tw = tid>>4. j = 6*td + jj (jj 0..5) covers j 0..95; j=96 separate.
    // Rs index i = w_local + 96 - j; per-thread pair-aligned base:
    // baseP = 8*tw - 6*td + 90 (even, >= 0; max float = 223 < RW).
    const int td = tid & 15;
    const int tw = tid >> 4;
    const float* RrowP = Rs + (8 * tw - 6 * td + 90);

    u64 Ae[3][4], Ao[3][3], Sp[3];
    #pragma unroll
    for (int j3 = 0; j3 < 3; j3++) {
        #pragma unroll
        for (int wp = 0; wp < 4; wp++) Ae[j3][wp] = 0ULL;
        #pragma unroll
        for (int p = 0; p < 3; p++)   Ao[j3][p] = 0ULL;
        Sp[j3] = 0ULL;
    }

    const float* __restrict__ LgT =
        Lg0 + ((size_t)(b * CC) * HH + h) * WWID + w0 + 8 * tw;

    // L prefetched one channel ahead (register double buffer); R unbuffered
    // (LDS latency covered by 16 warps/SM).
    u64 LA[4], LB[4];
    load_L(LgT, 0, LA);
    #pragma unroll 1
    for (int c = 0; c < CC; c += 2) {
        load_L(LgT, c + 1, LB);
        {
            u64 RP[7]; load_R(RrowP, c, RP);
            compute_c(Ae, Ao, Sp, LA, RP);
        }
        load_L(LgT, (c + 2 < CC) ? c + 2 : 0, LA);
        {
            u64 RP[7]; load_R(RrowP, c + 1, RP);
            compute_c(Ae, Ao, Sp, LB, RP);
        }
    }

    // ---------------- epilogue: scale by 1/64 and store -------------------
    const u64 scale2 = pack2(0x3C800000u, 0x3C800000u);  // (1/64, 1/64)
    float* outBase = out + (((size_t)b * DD) * HH + h) * WWID + w0 + 8 * tw;
    #pragma unroll
    for (int j3 = 0; j3 < 3; j3++) {
        {   // even jj = 2*j3
            int j = 6 * td + 2 * j3;
            float* o = outBase + (size_t)j * HSTRIDE;
            u64 v0 = mul2(Ae[j3][0], scale2), v1 = mul2(Ae[j3][1], scale2);
            *(uint4*)(o)     = make_uint4(lou(v0), hiu(v0), lou(v1), hiu(v1));
            u64 v2 = mul2(Ae[j3][2], scale2), v3 = mul2(Ae[j3][3], scale2);
            *(uint4*)(o + 4) = make_uint4(lou(v2), hiu(v2), lou(v3), hiu(v3));
        }
        {   // odd jj = 2*j3+1: {s0, o0.lo, o0.hi, o1.lo | o1.hi, o2.lo, o2.hi, s7}
            int j = 6 * td + 2 * j3 + 1;
            float* o = outBase + (size_t)j * HSTRIDE;
            u64 p0 = mul2(Ao[j3][0], scale2);
            u64 p1 = mul2(Ao[j3][1], scale2);
            u64 p2 = mul2(Ao[j3][2], scale2);
            u64 ss = mul2(Sp[j3], scale2);
            *(uint4*)(o)     = make_uint4(lou(ss), lou(p0), hiu(p0), lou(p1));
            *(uint4*)(o + 4) = make_uint4(hiu(p1), lou(p2), hiu(p2), hiu(ss));
        }
    }

    // ---------------- j = 96 plane (d = +48): i = w_local ------------------
    if (tid < WT) {
        const float* Lg96 = Lg0 + ((size_t)(b * CC) * HH + h) * WWID + w0 + tid;
        float s = 0.f;
        #pragma unroll 8
        for (int c = 0; c < CC; c++)
            s += Lg96[(size_t)c * HSTRIDE] * Rs[c * RW + tid];
        out[(((size_t)b * DD + 96) * HH + h) * WWID + w0 + tid] = s * 0.015625f;
    }
}

extern "C" void kernel_launch(void* const* d_in, const int* in_sizes, int n_in,
                              void* d_out, int out_size)
{
    const float* L = (const float*)d_in[0];
    const float* R = (const float*)d_in[1];
    float* out = (float*)d_out;
    cudaFuncSetAttribute(cost_volume_kernel,
                         cudaFuncAttributeMaxDynamicSharedMemorySize, SMEM_BYTES);
    dim3 grid(WWID / WT, HH, BB);   // (4, 256, 4) = 4096 CTAs
    cost_volume_kernel<<<grid, NTHREADS, SMEM_BYTES>>>(L, R, out);
}

// round 13
// speedup vs baseline: 1.0012x; 1.0005x over previous
#include <cuda_runtime.h>
#include <cstdint>

#define BB 4
#define CC 64
#define HH 256
#define WWID 512
#define MAXD 48
#define DD 97          // 2*MAXD+1
#define WT 128         // W tile per CTA
#define RW 224         // WT + 2*MAXD
#define NTHREADS 256
#define SMEM_BYTES (CC*RW*4)   // 57344 B (56 KB) — R tile only
#define HSTRIDE ((size_t)HH*WWID)

using u64 = unsigned long long;

__device__ __forceinline__ u64 pack2(unsigned lo, unsigned hi) {
    u64 d; asm("mov.b64 %0, {%1, %2};" : "=l"(d) : "r"(lo), "r"(hi)); return d;
}
__device__ __forceinline__ void unpack2(u64 v, unsigned &lo, unsigned &hi) {
    asm("mov.b64 {%0, %1}, %2;" : "=r"(lo), "=r"(hi) : "l"(v));
}
__device__ __forceinline__ void ffma2(u64 &acc, u64 a, u64 b) {
    asm("fma.rn.f32x2 %0, %1, %2, %0;" : "+l"(acc) : "l"(a), "l"(b));
}
__device__ __forceinline__ u64 mul2(u64 a, u64 b) {
    u64 d; asm("mul.rn.f32x2 %0, %1, %2;" : "=l"(d) : "l"(a), "l"(b)); return d;
}
__device__ __forceinline__ unsigned lou(u64 v){ unsigned a,b; unpack2(v,a,b); return a; }
__device__ __forceinline__ unsigned hiu(u64 v){ unsigned a,b; unpack2(v,a,b); return b; }

extern __shared__ float smem[];

// L: 8 floats via 2x LDG.128 (16 lanes share each address -> broadcast)
__device__ __forceinline__ void load_L(const float* __restrict__ LgT, int c, u64* L)
{
    ulonglong2 a = *(const ulonglong2*)(LgT + (size_t)c * HSTRIDE);
    ulonglong2 b = *(const ulonglong2*)(LgT + (size_t)c * HSTRIDE + 4);
    L[0] = a.x; L[1] = a.y; L[2] = b.x; L[3] = b.y;
}

// R: 14 floats as 7 aligned u64 pairs (LDS.64, half-warp conflict-free:
// (4tw - 3td + const + m) mod 16 distinct over td=0..15 since gcd(3,16)=1)
__device__ __forceinline__ void load_R(const float* RrowP, int c, u64* RP)
{
    #pragma unroll
    for (int m = 0; m < 7; m++)
        RP[m] = *(const u64*)(RrowP + c * RW + 2 * m);
}

// One channel: j = 6*td + jj, w = 8*tw + ww, r[t] at RP-float-offset t+1,
// t = ww + 5 - jj.
// even jj=2je: out pair (ww,ww+1), ww=2wp -> t odd -> native pair RP[wp+3-je]
// odd  jj=2jo+1: acc re-paired (2p+1,2p+2) -> native pair RP[p+3-jo];
//   ends: w=0 -> hi(RP[2-jo]), w=7 -> lo(RP[6-jo])
__device__ __forceinline__ void compute_c(u64 Ae[3][4], u64 Ao[3][3], u64 Sp[3],
                                          const u64* L, const u64* RP)
{
    u64 Lodd[3];
    Lodd[0] = pack2(hiu(L[0]), lou(L[1]));  // (l1,l2)
    Lodd[1] = pack2(hiu(L[1]), lou(L[2]));  // (l3,l4)
    Lodd[2] = pack2(hiu(L[2]), lou(L[3]));  // (l5,l6)
    u64 l07 = pack2(lou(L[0]), hiu(L[3]));  // (l0,l7)
    #pragma unroll
    for (int je = 0; je < 3; je++)
        #pragma unroll
        for (int wp = 0; wp < 4; wp++)
            ffma2(Ae[je][wp], L[wp], RP[wp + 3 - je]);
    #pragma unroll
    for (int jo = 0; jo < 3; jo++) {
        #pragma unroll
        for (int p = 0; p < 3; p++)
            ffma2(Ao[jo][p], Lodd[p], RP[p + 3 - jo]);
        u64 rr = pack2(hiu(RP[2 - jo]), lou(RP[6 - jo]));
        ffma2(Sp[jo], l07, rr);
    }
}

__global__ void __launch_bounds__(NTHREADS, 2)
cost_volume_kernel(const float* __restrict__ Lg0,
                   const float* __restrict__ Rg0,
                   float* __restrict__ out)
{
    float* Rs = smem;   // [CC][RW], Rs[c][i] = r[w0-48+i]

    const int w0  = blockIdx.x * WT;
    const int h   = blockIdx.y;
    const int b   = blockIdx.z;
    const int tid = threadIdx.x;

    // ---------------- stage R tile with zero-padded halo ----------------
    const float* Rg = Rg0 + ((size_t)(b * CC) * HH + h) * WWID;
    {
        const int NV = CC * RW / 4;   // 3584 float4
        #pragma unroll 2
        for (int idx = tid; idx < NV; idx += NTHREADS) {
            int c = idx / 56;
            int k = (idx - c * 56) << 2;
            int gw = w0 - MAXD + k;
            const float* rr = Rg + (size_t)c * HSTRIDE;
            float4 v;
            if (gw >= 0 && gw + 3 < WWID) {
                v = *(const float4*)(rr + gw);
            } else {
                v.x = (gw     >= 0 && gw     < WWID) ? rr[gw]     : 0.f;
                v.y = (gw + 1 >= 0 && gw + 1 < WWID) ? rr[gw + 1] : 0.f;
                v.z = (gw + 2 >= 0 && gw + 2 < WWID) ? rr[gw + 2] : 0.f;
                v.w = (gw + 3 >= 0 && gw + 3 < WWID) ? rr[gw + 3] : 0.f;
            }
            *(float4*)(Rs + c * RW + k) = v;
        }
    }
    __syncthreads();

    // ---------------- compute: 8(w) x 6(j) register tile per thread -------
    // td = tid&15 (j group; 16 adjacent lanes share tw -> L LDG broadcast),
    // tw = tid>>4. j = 6*td + jj (jj 0..5) covers j 0..95; j=96 separate.
    // Rs index i = w_local + 96 - j; per-thread pair-aligned base:
    // baseP = 8*tw - 6*td + 90 (even, >= 0; max float = 223 < RW).
    const int td = tid & 15;
    const int tw = tid >> 4;
    const float* RrowP = Rs + (8 * tw - 6 * td + 90);

    u64 Ae[3][4], Ao[3][3], Sp[3];
    #pragma unroll
    for (int j3 = 0; j3 < 3; j3++) {
        #pragma unroll
        for (int wp = 0; wp < 4; wp++) Ae[j3][wp] = 0ULL;
        #pragma unroll
        for (int p = 0; p < 3; p++)   Ao[j3][p] = 0ULL;
        Sp[j3] = 0ULL;
    }

    const float* __restrict__ LgT =
        Lg0 + ((size_t)(b * CC) * HH + h) * WWID + w0 + 8 * tw;

    // L prefetched one channel ahead (register double buffer); R unbuffered
    // (LDS latency covered by 16 warps/SM).
    u64 LA[4], LB[4];
    load_L(LgT, 0, LA);
    #pragma unroll 1
    for (int c = 0; c < CC; c += 2) {
        load_L(LgT, c + 1, LB);
        {
            u64 RP[7]; load_R(RrowP, c, RP);
            compute_c(Ae, Ao, Sp, LA, RP);
        }
        load_L(LgT, (c + 2 < CC) ? c + 2 : 0, LA);
        {
            u64 RP[7]; load_R(RrowP, c + 1, RP);
            compute_c(Ae, Ao, Sp, LB, RP);
        }
    }

    // ---------------- epilogue: scale by 1/64 and store -------------------
    const u64 scale2 = pack2(0x3C800000u, 0x3C800000u);  // (1/64, 1/64)
    float* outBase = out + (((size_t)b * DD) * HH + h) * WWID + w0 + 8 * tw;
    #pragma unroll
    for (int j3 = 0; j3 < 3; j3++) {
        {   // even jj = 2*j3
            int j = 6 * td + 2 * j3;
            float* o = outBase + (size_t)j * HSTRIDE;
            u64 v0 = mul2(Ae[j3][0], scale2), v1 = mul2(Ae[j3][1], scale2);
            *(uint4*)(o)     = make_uint4(lou(v0), hiu(v0), lou(v1), hiu(v1));
            u64 v2 = mul2(Ae[j3][2], scale2), v3 = mul2(Ae[j3][3], scale2);
            *(uint4*)(o + 4) = make_uint4(lou(v2), hiu(v2), lou(v3), hiu(v3));
        }
        {   // odd jj = 2*j3+1: {s0, o0.lo, o0.hi, o1.lo | o1.hi, o2.lo, o2.hi, s7}
            int j = 6 * td + 2 * j3 + 1;
            float* o = outBase + (size_t)j * HSTRIDE;
            u64 p0 = mul2(Ao[j3][0], scale2);
            u64 p1 = mul2(Ao[j3][1], scale2);
            u64 p2 = mul2(Ao[j3][2], scale2);
            u64 ss = mul2(Sp[j3], scale2);
            *(uint4*)(o)     = make_uint4(lou(ss), lou(p0), hiu(p0), lou(p1));
            *(uint4*)(o + 4) = make_uint4(hiu(p1), lou(p2), hiu(p2), hiu(ss));
        }
    }

    // ---------------- j = 96 plane (d = +48): i = w_local ------------------
    if (tid < WT) {
        const float* Lg96 = Lg0 + ((size_t)(b * CC) * HH + h) * WWID + w0 + tid;
        float s = 0.f;
        #pragma unroll 8
        for (int c = 0; c < CC; c++)
            s += Lg96[(size_t)c * HSTRIDE] * Rs[c * RW + tid];
        out[(((size_t)b * DD + 96) * HH + h) * WWID + w0 + tid] = s * 0.015625f;
    }
}

extern "C" void kernel_launch(void* const* d_in, const int* in_sizes, int n_in,
                              void* d_out, int out_size)
{
    const float* L = (const float*)d_in[0];
    const float* R = (const float*)d_in[1];
    float* out = (float*)d_out;
    cudaFuncSetAttribute(cost_volume_kernel,
                         cudaFuncAttributeMaxDynamicSharedMemorySize, SMEM_BYTES);
    dim3 grid(WWID / WT, HH, BB);   // (4, 256, 4) = 4096 CTAs
    cost_volume_kernel<<<grid, NTHREADS, SMEM_BYTES>>>(L, R, out);
}

// round 14
// speedup vs baseline: 1.3667x; 1.3650x over previous
#include <cuda_runtime.h>
#include <cstdint>

#define BB 4
#define CC 64
#define HH 256
#define WWID 512
#define MAXD 48
#define DD 97          // 2*MAXD+1
#define WT 128         // W tile per CTA
#define RW 224         // WT + 2*MAXD
#define NTHREADS 256
#define SMEM_BYTES ((CC*(WT+RW))*4)   // 90112 B -> 2 CTAs/SM = 16 warps
#define HSTRIDE ((size_t)HH*WWID)

using u64 = unsigned long long;

__device__ __forceinline__ u64 pack2(unsigned lo, unsigned hi) {
    u64 d; asm("mov.b64 %0, {%1, %2};" : "=l"(d) : "r"(lo), "r"(hi)); return d;
}
__device__ __forceinline__ void unpack2(u64 v, unsigned &lo, unsigned &hi) {
    asm("mov.b64 {%0, %1}, %2;" : "=r"(lo), "=r"(hi) : "l"(v));
}
__device__ __forceinline__ void ffma2(u64 &acc, u64 a, u64 b) {
    asm("fma.rn.f32x2 %0, %1, %2, %0;" : "+l"(acc) : "l"(a), "l"(b));
}
__device__ __forceinline__ u64 mul2(u64 a, u64 b) {
    u64 d; asm("mul.rn.f32x2 %0, %1, %2;" : "=l"(d) : "l"(a), "l"(b)); return d;
}
__device__ __forceinline__ unsigned lou(u64 v){ unsigned a,b; unpack2(v,a,b); return a; }
__device__ __forceinline__ unsigned hiu(u64 v){ unsigned a,b; unpack2(v,a,b); return b; }

extern __shared__ float smem[];

// L: 8 floats via 2x LDS.128 (16 adjacent lanes share each address ->
// broadcast, dedup'd by the smem crossbar; two tw groups per warp, no conflict)
__device__ __forceinline__ void load_L(const float* Lrow, int c, u64* L)
{
    ulonglong2 a = *(const ulonglong2*)(Lrow + c * WT);
    ulonglong2 b = *(const ulonglong2*)(Lrow + c * WT + 4);
    L[0] = a.x; L[1] = a.y; L[2] = b.x; L[3] = b.y;
}

// R: 14 floats as 7 aligned u64 pairs. LDS.64 half-warp: float offset
// -6td + const over td=0..15 hits all 16 even bank-pairs -> conflict-free.
__device__ __forceinline__ void load_R(const float* RrowP, int c, u64* RP)
{
    #pragma unroll
    for (int m = 0; m < 7; m++)
        RP[m] = *(const u64*)(RrowP + c * RW + 2 * m);
}

// One channel: j = 6*td + jj, w = 8*tw + ww, r[t] at RP-float-offset t+1,
// t = ww + 5 - jj.
// even jj=2je: out pair (ww,ww+1), ww=2wp -> native pair RP[wp+3-je]
// odd  jj=2jo+1: acc re-paired (2p+1,2p+2) -> native pair RP[p+3-jo];
//   ends: w=0 -> hi(RP[2-jo]), w=7 -> lo(RP[6-jo])
__device__ __forceinline__ void compute_c(u64 Ae[3][4], u64 Ao[3][3], u64 Sp[3],
                                          const u64* L, const u64* RP)
{
    u64 Lodd[3];
    Lodd[0] = pack2(hiu(L[0]), lou(L[1]));  // (l1,l2)
    Lodd[1] = pack2(hiu(L[1]), lou(L[2]));  // (l3,l4)
    Lodd[2] = pack2(hiu(L[2]), lou(L[3]));  // (l5,l6)
    u64 l07 = pack2(lou(L[0]), hiu(L[3]));  // (l0,l7)
    #pragma unroll
    for (int je = 0; je < 3; je++)
        #pragma unroll
        for (int wp = 0; wp < 4; wp++)
            ffma2(Ae[je][wp], L[wp], RP[wp + 3 - je]);
    #pragma unroll
    for (int jo = 0; jo < 3; jo++) {
        #pragma unroll
        for (int p = 0; p < 3; p++)
            ffma2(Ao[jo][p], Lodd[p], RP[p + 3 - jo]);
        u64 rr = pack2(hiu(RP[2 - jo]), lou(RP[6 - jo]));
        ffma2(Sp[jo], l07, rr);
    }
}

__global__ void __launch_bounds__(NTHREADS, 2)
cost_volume_kernel(const float* __restrict__ Lg0,
                   const float* __restrict__ Rg0,
                   float* __restrict__ out)
{
    float* Ls = smem;              // [CC][WT]
    float* Rs = smem + CC * WT;    // [CC][RW], Rs[c][i] = r[w0-48+i]

    const int w0  = blockIdx.x * WT;
    const int h   = blockIdx.y;
    const int b   = blockIdx.z;
    const int tid = threadIdx.x;

    // ---------------- stage L tile (coalesced float4, high MLP) ----------
    const float* Lg = Lg0 + ((size_t)(b * CC) * HH + h) * WWID + w0;
    {
        const int NV = CC * WT / 4;   // 2048 float4, 8 per thread
        #pragma unroll 4
        for (int idx = tid; idx < NV; idx += NTHREADS) {
            int c = idx >> 5;
            int k = (idx & 31) << 2;
            float4 v = *(const float4*)(Lg + (size_t)c * HSTRIDE + k);
            *(float4*)(Ls + c * WT + k) = v;
        }
    }
    // ---------------- stage R tile with zero-padded halo ------------------
    const float* Rg = Rg0 + ((size_t)(b * CC) * HH + h) * WWID;
    {
        const int NV = CC * RW / 4;   // 3584 float4, 14 per thread
        #pragma unroll 4
        for (int idx = tid; idx < NV; idx += NTHREADS) {
            int c = idx / 56;
            int k = (idx - c * 56) << 2;
            int gw = w0 - MAXD + k;
            const float* rr = Rg + (size_t)c * HSTRIDE;
            float4 v;
            if (gw >= 0 && gw + 3 < WWID) {
                v = *(const float4*)(rr + gw);
            } else {
                v.x = (gw     >= 0 && gw     < WWID) ? rr[gw]     : 0.f;
                v.y = (gw + 1 >= 0 && gw + 1 < WWID) ? rr[gw + 1] : 0.f;
                v.z = (gw + 2 >= 0 && gw + 2 < WWID) ? rr[gw + 2] : 0.f;
                v.w = (gw + 3 >= 0 && gw + 3 < WWID) ? rr[gw + 3] : 0.f;
            }
            *(float4*)(Rs + c * RW + k) = v;
        }
    }
    __syncthreads();

    // ---------------- compute: 8(w) x 6(j) register tile per thread -------
    // td = tid&15 (j group), tw = tid>>4 (w group). j = 6*td + jj (jj 0..5)
    // covers j 0..95; j=96 handled separately. Rs index i = w_local + 96 - j;
    // pair-aligned per-thread base = 8*tw - 6*td + 90 (even, in [0, 210]).
    const int td = tid & 15;
    const int tw = tid >> 4;
    const float* RrowP = Rs + (8 * tw - 6 * td + 90);
    const float* Lrow  = Ls + 8 * tw;

    u64 Ae[3][4], Ao[3][3], Sp[3];
    #pragma unroll
    for (int j3 = 0; j3 < 3; j3++) {
        #pragma unroll
        for (int wp = 0; wp < 4; wp++) Ae[j3][wp] = 0ULL;
        #pragma unroll
        for (int p = 0; p < 3; p++)   Ao[j3][p] = 0ULL;
        Sp[j3] = 0ULL;
    }

    // All-smem mainloop; 29-cyc LDS latency covered by 4 warps/SMSP.
    // Unroll 2 so ptxas front-batches the next channel's loads.
    #pragma unroll 2
    for (int c = 0; c < CC; c++) {
        u64 L[4];  load_L(Lrow, c, L);
        u64 RP[7]; load_R(RrowP, c, RP);
        compute_c(Ae, Ao, Sp, L, RP);
    }

    // ---------------- epilogue: scale by 1/64 and store -------------------
    const u64 scale2 = pack2(0x3C800000u, 0x3C800000u);  // (1/64, 1/64)
    float* outBase = out + (((size_t)b * DD) * HH + h) * WWID + w0 + 8 * tw;
    #pragma unroll
    for (int j3 = 0; j3 < 3; j3++) {
        {   // even jj = 2*j3
            int j = 6 * td + 2 * j3;
            float* o = outBase + (size_t)j * HSTRIDE;
            u64 v0 = mul2(Ae[j3][0], scale2), v1 = mul2(Ae[j3][1], scale2);
            *(uint4*)(o)     = make_uint4(lou(v0), hiu(v0), lou(v1), hiu(v1));
            u64 v2 = mul2(Ae[j3][2], scale2), v3 = mul2(Ae[j3][3], scale2);
            *(uint4*)(o + 4) = make_uint4(lou(v2), hiu(v2), lou(v3), hiu(v3));
        }
        {   // odd jj = 2*j3+1: {s0, o0.lo, o0.hi, o1.lo | o1.hi, o2.lo, o2.hi, s7}
            int j = 6 * td + 2 * j3 + 1;
            float* o = outBase + (size_t)j * HSTRIDE;
            u64 p0 = mul2(Ao[j3][0], scale2);
            u64 p1 = mul2(Ao[j3][1], scale2);
            u64 p2 = mul2(Ao[j3][2], scale2);
            u64 ss = mul2(Sp[j3], scale2);
            *(uint4*)(o)     = make_uint4(lou(ss), lou(p0), hiu(p0), lou(p1));
            *(uint4*)(o + 4) = make_uint4(hiu(p1), lou(p2), hiu(p2), hiu(ss));
        }
    }

    // ---------------- j = 96 plane (d = +48): i = w_local ------------------
    if (tid < WT) {
        float s = 0.f;
        #pragma unroll 8
        for (int c = 0; c < CC; c++)
            s += Ls[c * WT + tid] * Rs[c * RW + tid];
        out[(((size_t)b * DD + 96) * HH + h) * WWID + w0 + tid] = s * 0.015625f;
    }
}

extern "C" void kernel_launch(void* const* d_in, const int* in_sizes, int n_in,
                              void* d_out, int out_size)
{
    const float* L = (const float*)d_in[0];
    const float* R = (const float*)d_in[1];
    float* out = (float*)d_out;
    cudaFuncSetAttribute(cost_volume_kernel,
                         cudaFuncAttributeMaxDynamicSharedMemorySize, SMEM_BYTES);
    dim3 grid(WWID / WT, HH, BB);   // (4, 256, 4) = 4096 CTAs
    cost_volume_kernel<<<grid, NTHREADS, SMEM_BYTES>>>(L, R, out);
}